// round 2
// baseline (speedup 1.0000x reference)
#include <cuda_runtime.h>
#include <cuda_fp16.h>

#define B_  2
#define H_  16
#define S_  8192
#define D_  128
#define NT  (B_*H_*S_)      /* 262144 rows per tensor */
#define QS  136             /* smem row stride in halves (pad 128->136: conflict-free ldmatrix) */

__device__ __align__(16) float  g_Q[128*128];
__device__ __align__(16) __half g_Qhi[128*128];
__device__ __align__(16) __half g_Qlo[128*128];
__device__ __align__(16) __half g_QThi[128*128];
__device__ __align__(16) __half g_QTlo[128*128];

// ---------------------------------------------------------------------------
// Kernel 1: build Q (fp32) from Householder vectors, column-parallel.
// Q starts as I; for each v: Q[:,j] -= (2/(v.v+1e-8)) * (v . Q[:,j]) * v.
// 16 blocks x 128 threads. col = bid*8 + t/16; 16 lanes per column, each
// lane owns 8 contiguous row-elements of its column in registers.
// ---------------------------------------------------------------------------
__global__ void build_q_kernel(const float* __restrict__ vs)
{
    __shared__ float svs[64*128];
    const int t = threadIdx.x;
    for (int i = t; i < 64*128; i += 128) svs[i] = vs[i];
    __syncthreads();

    const int col = blockIdx.x * 8 + (t >> 4);
    const int ip  = t & 15;

    float qc[8];
#pragma unroll
    for (int j = 0; j < 8; j++) qc[j] = (ip*8 + j == col) ? 1.0f : 0.0f;

    for (int r = 0; r < 64; r++) {
        const float* v = &svs[r*128 + ip*8];
        float w = 0.0f, nn = 0.0f;
#pragma unroll
        for (int j = 0; j < 8; j++) { w += v[j]*qc[j]; nn += v[j]*v[j]; }
#pragma unroll
        for (int off = 8; off; off >>= 1) {
            w  += __shfl_xor_sync(0xffffffffu, w,  off);
            nn += __shfl_xor_sync(0xffffffffu, nn, off);
        }
        const float sw = 2.0f/(nn + 1e-8f) * w;
#pragma unroll
        for (int j = 0; j < 8; j++) qc[j] -= sw * v[j];
    }
#pragma unroll
    for (int j = 0; j < 8; j++) g_Q[(ip*8 + j)*128 + col] = qc[j];
}

// ---------------------------------------------------------------------------
// Kernel 2: split Q into fp16 hi/lo, and build transposed copies.
// g_Qhi/lo[i]  : Q row-major   (used as B of GEMM1: B[n=e][k=d] = Q[e][d])
// g_QThi/lo[i] : Q^T row-major (used as B of GEMM2: B[n=f][k=e] = Q[e][f])
// ---------------------------------------------------------------------------
__global__ void split_q_kernel()
{
    const int i = blockIdx.x * blockDim.x + threadIdx.x;   // 16384 total
    const float x = g_Q[i];
    const __half h = __float2half_rn(x);
    g_Qhi[i] = h;
    g_Qlo[i] = __float2half_rn(x - __half2float(h));
    const float xt = g_Q[(i & 127)*128 + (i >> 7)];
    const __half ht = __float2half_rn(xt);
    g_QThi[i] = ht;
    g_QTlo[i] = __float2half_rn(xt - __half2float(ht));
}

// ---------------------------------------------------------------------------
// mma/ldmatrix helpers
// ---------------------------------------------------------------------------
__device__ __forceinline__ unsigned su32(const void* p)
{
    return (unsigned)__cvta_generic_to_shared(p);
}
__device__ __forceinline__ void ldsm4(unsigned r[4], unsigned a)
{
    asm volatile("ldmatrix.sync.aligned.m8n8.x4.shared.b16 {%0,%1,%2,%3}, [%4];\n"
                 : "=r"(r[0]), "=r"(r[1]), "=r"(r[2]), "=r"(r[3]) : "r"(a));
}
__device__ __forceinline__ void mma16816(float c[4],
                                         unsigned a0, unsigned a1, unsigned a2, unsigned a3,
                                         unsigned b0, unsigned b1)
{
    asm volatile("mma.sync.aligned.m16n8k16.row.col.f32.f16.f16.f32 "
                 "{%0,%1,%2,%3}, {%4,%5,%6,%7}, {%8,%9}, {%0,%1,%2,%3};\n"
                 : "+f"(c[0]), "+f"(c[1]), "+f"(c[2]), "+f"(c[3])
                 : "r"(a0), "r"(a1), "r"(a2), "r"(a3), "r"(b0), "r"(b1));
}
__device__ __forceinline__ unsigned h2hi(float a, float b)
{
    __half2 h = __floats2half2_rn(a, b);
    return *reinterpret_cast<unsigned*>(&h);
}
__device__ __forceinline__ unsigned h2lo(float a, float b, unsigned hibits)
{
    __half2 hh = *reinterpret_cast<__half2*>(&hibits);
    float2 hf = __half22float2(hh);
    __half2 l = __floats2half2_rn(a - hf.x, b - hf.y);
    return *reinterpret_cast<unsigned*>(&l);
}

// ---------------------------------------------------------------------------
// Main fused kernel. One CTA = 128 token rows (8 warps x 16 rows x 128 cols).
//   GEMM1: y = x @ Q^T (3-pass fp16-split mma, fp32 accum)
//   RoPE : in registers (partner (e, e+64) = acc[nt], acc[nt+8], same slot;
//          cos/sin[e+64] == cos/sin[e], so only e<64 values loaded)
//   GEMM2: out = z @ Q, A-fragments built directly from C registers
// ---------------------------------------------------------------------------
__global__ __launch_bounds__(256, 1)
void rnrope_main(const float* __restrict__ qg, const float* __restrict__ kg,
                 const float* __restrict__ cosg, const float* __restrict__ sing,
                 float* __restrict__ out)
{
    extern __shared__ __half sm[];
    __half* sQhi  = sm;
    __half* sQlo  = sm + 128*QS;
    __half* sQThi = sm + 2*128*QS;
    __half* sQTlo = sm + 3*128*QS;

    const int tid = threadIdx.x;

    // cooperative load of Q/QT hi/lo into padded smem
    for (int i = tid; i < 128*16; i += 256) {
        const int row = i >> 4;
        const int ch  = (i & 15) * 8;
        *(uint4*)&sQhi [row*QS + ch] = *(const uint4*)&g_Qhi [row*128 + ch];
        *(uint4*)&sQlo [row*QS + ch] = *(const uint4*)&g_Qlo [row*128 + ch];
        *(uint4*)&sQThi[row*QS + ch] = *(const uint4*)&g_QThi[row*128 + ch];
        *(uint4*)&sQTlo[row*QS + ch] = *(const uint4*)&g_QTlo[row*128 + ch];
    }
    __syncthreads();

    const int warp = tid >> 5;
    const int lane = tid & 31;
    const int u = lane & 3;        // t%4
    const int g = lane >> 2;       // groupID

    const int base  = blockIdx.x * 128;                 // global out row of tile
    const int local = (base < NT) ? base : base - NT;   // row within tensor
    const float* x  = (base < NT) ? qg : kg;

    const float* A0 = x + (size_t)(local + warp*16 + g) * 128;
    const float* A1 = A0 + 8*128;

    const int b   = local >> 17;                        // H*S = 131072 = 2^17
    const int csr = (b << 13) + (local & 8191) + warp*16 + g;
    const float* C0  = cosg + (size_t)csr * 128;
    const float* C1  = C0 + 8*128;
    const float* Sn0 = sing + (size_t)csr * 128;
    const float* Sn1 = Sn0 + 8*128;

    // per-lane ldmatrix base offset (halves):
    //  mat m = lane/8; row-in-tile = (m>>1)*8 + lane%8; col-in-tile = (m&1)*8
    const int lrow = ((lane >> 4) << 3) + (lane & 7);
    const int lcol = ((lane >> 3) & 1) << 3;
    const int lbo  = lrow*QS + lcol;

    float acc[16][4];
#pragma unroll
    for (int n = 0; n < 16; n++)
#pragma unroll
        for (int i = 0; i < 4; i++) acc[n][i] = 0.0f;

    // ---------------- GEMM1: y = x @ Q^T ----------------
#pragma unroll
    for (int kt = 0; kt < 8; kt++) {
        const float2 x00 = *(const float2*)&A0[kt*16 + 2*u];
        const float2 x01 = *(const float2*)&A0[kt*16 + 2*u + 8];
        const float2 x10 = *(const float2*)&A1[kt*16 + 2*u];
        const float2 x11 = *(const float2*)&A1[kt*16 + 2*u + 8];
        const unsigned ah0 = h2hi(x00.x, x00.y), ah1 = h2hi(x10.x, x10.y);
        const unsigned ah2 = h2hi(x01.x, x01.y), ah3 = h2hi(x11.x, x11.y);
        const unsigned al0 = h2lo(x00.x, x00.y, ah0), al1 = h2lo(x10.x, x10.y, ah1);
        const unsigned al2 = h2lo(x01.x, x01.y, ah2), al3 = h2lo(x11.x, x11.y, ah3);
#pragma unroll
        for (int np = 0; np < 8; np++) {
            unsigned bh[4], bl[4];
            ldsm4(bh, su32(sQhi + lbo + np*(16*QS) + kt*16));
            ldsm4(bl, su32(sQlo + lbo + np*(16*QS) + kt*16));
            mma16816(acc[2*np],   ah0, ah1, ah2, ah3, bh[0], bh[1]);
            mma16816(acc[2*np],   ah0, ah1, ah2, ah3, bl[0], bl[1]);
            mma16816(acc[2*np],   al0, al1, al2, al3, bh[0], bh[1]);
            mma16816(acc[2*np+1], ah0, ah1, ah2, ah3, bh[2], bh[3]);
            mma16816(acc[2*np+1], ah0, ah1, ah2, ah3, bl[2], bl[3]);
            mma16816(acc[2*np+1], al0, al1, al2, al3, bh[2], bh[3]);
        }
    }

    // ---------------- RoPE in registers ----------------
#pragma unroll
    for (int nt = 0; nt < 8; nt++) {
        const float2 cA = *(const float2*)&C0 [nt*8 + 2*u];
        const float2 cB = *(const float2*)&C1 [nt*8 + 2*u];
        const float2 sA = *(const float2*)&Sn0[nt*8 + 2*u];
        const float2 sB = *(const float2*)&Sn1[nt*8 + 2*u];
        const float t0 = acc[nt][0], t1 = acc[nt][1];
        const float t2 = acc[nt][2], t3 = acc[nt][3];
        acc[nt][0]   = t0*cA.x - acc[nt+8][0]*sA.x;
        acc[nt][1]   = t1*cA.y - acc[nt+8][1]*sA.y;
        acc[nt][2]   = t2*cB.x - acc[nt+8][2]*sB.x;
        acc[nt][3]   = t3*cB.y - acc[nt+8][3]*sB.y;
        acc[nt+8][0] = acc[nt+8][0]*cA.x + t0*sA.x;
        acc[nt+8][1] = acc[nt+8][1]*cA.y + t1*sA.y;
        acc[nt+8][2] = acc[nt+8][2]*cB.x + t2*sB.x;
        acc[nt+8][3] = acc[nt+8][3]*cB.y + t3*sB.y;
    }

    // ---------------- GEMM2: out = z @ Q ----------------
    float o[16][4];
#pragma unroll
    for (int n = 0; n < 16; n++)
#pragma unroll
        for (int i = 0; i < 4; i++) o[n][i] = 0.0f;

#pragma unroll
    for (int kt = 0; kt < 8; kt++) {
        // A fragment for k-tile kt comes straight from C regs of GEMM1
        const unsigned ah0 = h2hi(acc[2*kt][0],   acc[2*kt][1]);
        const unsigned ah1 = h2hi(acc[2*kt][2],   acc[2*kt][3]);
        const unsigned ah2 = h2hi(acc[2*kt+1][0], acc[2*kt+1][1]);
        const unsigned ah3 = h2hi(acc[2*kt+1][2], acc[2*kt+1][3]);
        const unsigned al0 = h2lo(acc[2*kt][0],   acc[2*kt][1],   ah0);
        const unsigned al1 = h2lo(acc[2*kt][2],   acc[2*kt][3],   ah1);
        const unsigned al2 = h2lo(acc[2*kt+1][0], acc[2*kt+1][1], ah2);
        const unsigned al3 = h2lo(acc[2*kt+1][2], acc[2*kt+1][3], ah3);
#pragma unroll
        for (int np = 0; np < 8; np++) {
            unsigned bh[4], bl[4];
            ldsm4(bh, su32(sQThi + lbo + np*(16*QS) + kt*16));
            ldsm4(bl, su32(sQTlo + lbo + np*(16*QS) + kt*16));
            mma16816(o[2*np],   ah0, ah1, ah2, ah3, bh[0], bh[1]);
            mma16816(o[2*np],   ah0, ah1, ah2, ah3, bl[0], bl[1]);
            mma16816(o[2*np],   al0, al1, al2, al3, bh[0], bh[1]);
            mma16816(o[2*np+1], ah0, ah1, ah2, ah3, bh[2], bh[3]);
            mma16816(o[2*np+1], ah0, ah1, ah2, ah3, bl[2], bl[3]);
            mma16816(o[2*np+1], al0, al1, al2, al3, bh[2], bh[3]);
        }
    }

    // ---------------- store ----------------
    float* O0 = out + (size_t)(base + warp*16 + g) * 128;
    float* O1 = O0 + 8*128;
#pragma unroll
    for (int nt = 0; nt < 16; nt++) {
        *(float2*)&O0[nt*8 + 2*u] = make_float2(o[nt][0], o[nt][1]);
        *(float2*)&O1[nt*8 + 2*u] = make_float2(o[nt][2], o[nt][3]);
    }
}

// ---------------------------------------------------------------------------
extern "C" void kernel_launch(void* const* d_in, const int* in_sizes, int n_in,
                              void* d_out, int out_size)
{
    (void)in_sizes; (void)n_in; (void)out_size;
    const float* q    = (const float*)d_in[0];
    const float* k    = (const float*)d_in[1];
    const float* vs   = (const float*)d_in[2];
    const float* cosg = (const float*)d_in[3];
    const float* sing = (const float*)d_in[4];
    float* out = (float*)d_out;

    build_q_kernel<<<16, 128>>>(vs);
    split_q_kernel<<<64, 256>>>();

    const int SMEM = 4 * 128 * QS * (int)sizeof(__half);   // 139264 bytes
    cudaFuncSetAttribute(rnrope_main, cudaFuncAttributeMaxDynamicSharedMemorySize, SMEM);
    rnrope_main<<<4096, 256, SMEM>>>(q, k, cosg, sing, out);
}